// round 2
// baseline (speedup 1.0000x reference)
#include <cuda_runtime.h>

// Blur (upfirdn2d up=2, 4x4 kernel, down=2) collapses to a 2x2 cross-correlation
// with the odd-position taps of the 4x4 filter:
//   out[y,x] = f[1,1]*x[y,x] + f[1,3]*x[y,x+1] + f[3,1]*x[y+1,x] + f[3,3]*x[y+1,x+1]
// (zero outside the high edge).
//
// Shapes: x (8,256,128,128) f32, filt (256,1,4,4) f32, out (8,256,128,128) f32.
// One warp per (b,c,y) row: W=128 = 32 lanes * float4.

static constexpr int B = 8;
static constexpr int C = 256;
static constexpr int H = 128;
static constexpr int W = 128;
static constexpr int NROWS = B * C * H;            // 262144 warps
static constexpr int WARPS_PER_BLOCK = 8;          // 256 threads -> 8 consecutive rows/block
static constexpr int NBLOCKS = NROWS / WARPS_PER_BLOCK;

__global__ __launch_bounds__(WARPS_PER_BLOCK * 32)
void blur_kernel(const float* __restrict__ x,
                 const float* __restrict__ filt,
                 float* __restrict__ out) {
    const int warp = (blockIdx.x * WARPS_PER_BLOCK) + (threadIdx.x >> 5);
    const int lane = threadIdx.x & 31;

    const int y = warp & (H - 1);          // row within image
    const int c = (warp >> 7) & (C - 1);   // channel (H==128 -> >>7)

    // Per-channel taps at odd kernel positions (4x4 row-major: idx = ty*4+tx)
    const float* fw = filt + c * 16;
    const float wa = __ldg(fw + 5);    // f[1,1] -> x[y,x]
    const float wb = __ldg(fw + 7);    // f[1,3] -> x[y,x+1]
    const float wc = __ldg(fw + 13);   // f[3,1] -> x[y+1,x]
    const float wd = __ldg(fw + 15);   // f[3,3] -> x[y+1,x+1]

    const float4* row0 = reinterpret_cast<const float4*>(x) + (size_t)warp * (W / 4);
    float4 r0 = __ldg(row0 + lane);

    float4 r1 = make_float4(0.f, 0.f, 0.f, 0.f);
    if (y < H - 1) {                       // warp-uniform branch
        r1 = __ldg(row0 + (W / 4) + lane); // next row, same (b,c)
    }

    // x+1 neighbor across the lane boundary
    float e0 = __shfl_down_sync(0xffffffffu, r0.x, 1);
    float e1 = __shfl_down_sync(0xffffffffu, r1.x, 1);
    if (lane == 31) { e0 = 0.f; e1 = 0.f; } // past x = W-1 is zero

    float4 o;
    o.x = wa * r0.x + wb * r0.y + wc * r1.x + wd * r1.y;
    o.y = wa * r0.y + wb * r0.z + wc * r1.y + wd * r1.z;
    o.z = wa * r0.z + wb * r0.w + wc * r1.z + wd * r1.w;
    o.w = wa * r0.w + wb * e0   + wc * r1.w + wd * e1;

    reinterpret_cast<float4*>(out)[(size_t)warp * (W / 4) + lane] = o;
}

extern "C" void kernel_launch(void* const* d_in, const int* in_sizes, int n_in,
                              void* d_out, int out_size) {
    const float* x    = (const float*)d_in[0];
    const float* filt = (const float*)d_in[1];
    float* out = (float*)d_out;
    blur_kernel<<<NBLOCKS, WARPS_PER_BLOCK * 32>>>(x, filt, out);
}

// round 3
// speedup vs baseline: 1.2428x; 1.2428x over previous
#include <cuda_runtime.h>

// Blur (upfirdn2d up=2, 4x4 kernel, down=2) == 2x2 cross-correlation with the
// odd-position taps of the 4x4 filter:
//   out[y,x] = f[1,1]*x[y,x] + f[1,3]*x[y,x+1] + f[3,1]*x[y+1,x] + f[3,3]*x[y+1,x+1]
// (zero past the high edge).
//
// R2: register-block 4 rows per warp. Loads rows y..y+4 (5 float4 loads),
// produces rows y..y+3. The y+1 operand of row i is row i+1's load -> L1
// wavefronts per output row drop ~3x vs the 1-row/warp version, and MLP=5.

static constexpr int B = 8;
static constexpr int C = 256;
static constexpr int H = 128;
static constexpr int W = 128;
static constexpr int RPW = 4;                       // rows per warp
static constexpr int W4 = W / 4;                    // 32 float4 per row
static constexpr int NROWS = B * C * H;             // 262144
static constexpr int WARPS_PER_BLOCK = 8;           // 8 warps -> 32 consecutive rows/block
static constexpr int NBLOCKS = NROWS / (RPW * WARPS_PER_BLOCK);  // 8192

__global__ __launch_bounds__(WARPS_PER_BLOCK * 32)
void blur_kernel(const float* __restrict__ x,
                 const float* __restrict__ filt,
                 float* __restrict__ out) {
    const int warp = blockIdx.x * WARPS_PER_BLOCK + (threadIdx.x >> 5);
    const int lane = threadIdx.x & 31;

    const int row0 = warp * RPW;                 // first global row of this strip
    const int y0   = row0 & (H - 1);             // row within image
    const int c    = (row0 >> 7) & (C - 1);      // channel (H==128 -> >>7)

    // Per-channel taps at odd kernel positions (4x4 row-major: idx = ty*4+tx)
    const float* fw = filt + c * 16;
    const float wa = __ldg(fw + 5);    // f[1,1] -> x[y,x]
    const float wb = __ldg(fw + 7);    // f[1,3] -> x[y,x+1]
    const float wc = __ldg(fw + 13);   // f[3,1] -> x[y+1,x]
    const float wd = __ldg(fw + 15);   // f[3,3] -> x[y+1,x+1]

    const float4* p = reinterpret_cast<const float4*>(x) + (size_t)row0 * W4 + lane;

    // Front-batched loads: 5 rows in flight (MLP=5)
    float4 r[RPW + 1];
#pragma unroll
    for (int i = 0; i < RPW; i++) r[i] = __ldg(p + i * W4);
    r[RPW] = make_float4(0.f, 0.f, 0.f, 0.f);
    if (y0 + RPW < H)                             // warp-uniform branch
        r[RPW] = __ldg(p + RPW * W4);

    // x+1 neighbor across the lane boundary for each row
    float e[RPW + 1];
#pragma unroll
    for (int i = 0; i <= RPW; i++)
        e[i] = __shfl_down_sync(0xffffffffu, r[i].x, 1);
    if (lane == 31) {
#pragma unroll
        for (int i = 0; i <= RPW; i++) e[i] = 0.f;  // past x = W-1 is zero
    }

    float4* q = reinterpret_cast<float4*>(out) + (size_t)row0 * W4 + lane;
#pragma unroll
    for (int i = 0; i < RPW; i++) {
        float4 o;
        o.x = wa * r[i].x + wb * r[i].y + wc * r[i+1].x + wd * r[i+1].y;
        o.y = wa * r[i].y + wb * r[i].z + wc * r[i+1].y + wd * r[i+1].z;
        o.z = wa * r[i].z + wb * r[i].w + wc * r[i+1].z + wd * r[i+1].w;
        o.w = wa * r[i].w + wb * e[i]   + wc * r[i+1].w + wd * e[i+1];
        q[i * W4] = o;
    }
}

extern "C" void kernel_launch(void* const* d_in, const int* in_sizes, int n_in,
                              void* d_out, int out_size) {
    const float* x    = (const float*)d_in[0];
    const float* filt = (const float*)d_in[1];
    float* out = (float*)d_out;
    blur_kernel<<<NBLOCKS, WARPS_PER_BLOCK * 32>>>(x, filt, out);
}